// round 6
// baseline (speedup 1.0000x reference)
#include <cuda_runtime.h>
#include <stdint.h>

#define BB 8
#define NN 16384
#define SS 2048
#define CC 64
#define KK 32
#define COUT (3 + CC)      // 67
#define QW 8               // centers (warps) per query block
#define TILE 1024          // points per smem tile
#define NT (NN / TILE)     // 16 tiles

// Scratch for ball-query indices (no cudaMalloc allowed).
__device__ __align__(16) int g_idx[BB * SS * KK];

// ---------------------------------------------------------------------------
// Kernel 1: ball query. 8 warps (8 centers, same batch) per block share
// SoA point tiles staged in shared memory. Per warp: 128 points per step via
// 3 conflict-free LDS.128; 4 ballots; exact (non-FMA) distance math.
// Semantics: smallest 32 indices j with |c-p_j|^2 < 0.04 (ascending),
// padded with the first found index, or 0 if none found.
// ---------------------------------------------------------------------------
__global__ __launch_bounds__(256) void ball_query_kernel(
    const float4* __restrict__ points4,  // (B, N, 3) viewed as float4
    const float*  __restrict__ centers)  // (B, S, 3)
{
    __shared__ float sx[TILE], sy[TILE], sz[TILE];
    __shared__ int   sel[QW][KK];

    const int tid  = threadIdx.x;
    const int wid  = tid >> 5;
    const int lane = tid & 31;
    const int gw   = blockIdx.x * QW + wid;        // center id = b*S + s
    const int b    = blockIdx.x / (SS / QW);       // 256 blocks per batch

    const float* cptr = centers + (size_t)gw * 3;
    const float cx = __ldg(cptr + 0);
    const float cy = __ldg(cptr + 1);
    const float cz = __ldg(cptr + 2);

    const float4* pb4 = points4 + (size_t)b * (NN * 3 / 4);
    const float R2 = 0.04f;
    const unsigned below = (1u << lane) - 1u;

    int  cnt    = 0;
    bool mydone = false;

    for (int t = 0; t < NT; ++t) {
        if (__syncthreads_and((int)mydone)) break;

        // --- cooperative load: tile floats [t*3072, t*3072+3072) as 768 f4 ---
        #pragma unroll
        for (int k = 0; k < 3; ++k) {
            const int l4 = tid + k * 256;               // 0..767
            const float4 f = __ldg(pb4 + (size_t)t * 768 + l4);
            const int lf = 4 * l4;                      // local float base
            // float lf+m belongs to point (lf+m)/3, component (lf+m)%3
            #pragma unroll
            for (int m = 0; m < 4; ++m) {
                const int e  = lf + m;
                const int lp = e / 3;
                const int c  = e - 3 * lp;
                const float v = (m == 0) ? f.x : (m == 1) ? f.y : (m == 2) ? f.z : f.w;
                if (c == 0) sx[lp] = v;
                else if (c == 1) sy[lp] = v;
                else sz[lp] = v;
            }
        }
        __syncthreads();

        if (!mydone) {
            #pragma unroll 1
            for (int s = 0; s < TILE / 128; ++s) {
                const int f4i = s * 32 + lane;
                const float4 fx = ((const float4*)sx)[f4i];
                const float4 fy = ((const float4*)sy)[f4i];
                const float4 fz = ((const float4*)sz)[f4i];

                float dx, dy, dz;
                #define DIST(PX,PY,PZ,DST)                                         \
                    dx = __fadd_rn(cx, -(PX)); dy = __fadd_rn(cy, -(PY));          \
                    dz = __fadd_rn(cz, -(PZ));                                     \
                    DST = __fadd_rn(__fadd_rn(__fmul_rn(dx,dx), __fmul_rn(dy,dy)), \
                                    __fmul_rn(dz,dz));
                float q0, q1, q2, q3;
                DIST(fx.x, fy.x, fz.x, q0);
                DIST(fx.y, fy.y, fz.y, q1);
                DIST(fx.z, fy.z, fz.z, q2);
                DIST(fx.w, fy.w, fz.w, q3);
                #undef DIST

                const bool h0 = q0 < R2, h1 = q1 < R2, h2 = q2 < R2, h3 = q3 < R2;
                const unsigned m0 = __ballot_sync(0xffffffffu, h0);
                const unsigned m1 = __ballot_sync(0xffffffffu, h1);
                const unsigned m2 = __ballot_sync(0xffffffffu, h2);
                const unsigned m3 = __ballot_sync(0xffffffffu, h3);

                // ascending index order: j = t*1024 + s*128 + 4*lane + c
                int p = cnt + __popc(m0 & below) + __popc(m1 & below)
                            + __popc(m2 & below) + __popc(m3 & below);
                const int j = t * TILE + s * 128 + 4 * lane;
                if (h0) { if (p < KK) sel[wid][p] = j + 0; p++; }
                if (h1) { if (p < KK) sel[wid][p] = j + 1; p++; }
                if (h2) { if (p < KK) sel[wid][p] = j + 2; p++; }
                if (h3) { if (p < KK) sel[wid][p] = j + 3; p++; }

                cnt += __popc(m0) + __popc(m1) + __popc(m2) + __popc(m3);
                if (cnt >= KK) { mydone = true; break; }   // warp-uniform
            }
        }
        __syncthreads();
    }
    __syncwarp();

    int v;
    if (cnt == 0) {
        v = 0;
    } else {
        const int first = sel[wid][0];
        v = (lane < cnt) ? sel[wid][lane] : first;
    }
    g_idx[(size_t)gw * KK + lane] = v;
}

// ---------------------------------------------------------------------------
// Kernel 2: gather. Two blocks per (b, out-channel) plane (halves wave-
// quantization tail). Each block stages the 64KB source row in dynamic smem
// (re-reads are L2 hits), gathers via LDS, writes coalesced float4.
// ---------------------------------------------------------------------------
__global__ __launch_bounds__(512) void gather_kernel(
    const float* __restrict__ points,   // (B, N, 3)
    const float* __restrict__ centers,  // (B, S, 3)
    const float* __restrict__ feats,    // (B, C, N)
    float* __restrict__ out)            // (B, 67, S, K)
{
    extern __shared__ float row[];      // NN floats = 64KB

    const int chunk = blockIdx.x;       // 0 .. B*67*2-1
    const int plane = chunk >> 1;
    const int half  = chunk & 1;
    const int b  = plane / COUT;
    const int co = plane % COUT;
    const bool isxyz = (co < 3);

    if (isxyz) {
        const float* p = points + (size_t)b * NN * 3 + co;
        for (int i = threadIdx.x; i < NN; i += blockDim.x)
            row[i] = __ldg(p + 3 * i);
    } else {
        const float4* f4 = (const float4*)(feats + ((size_t)b * CC + (co - 3)) * NN);
        float4* r4 = (float4*)row;
        for (int i = threadIdx.x; i < NN / 4; i += blockDim.x)
            r4[i] = __ldg(f4 + i);
    }
    __syncthreads();

    const int4*  idx4 = (const int4*)(g_idx + (size_t)b * SS * KK);
    float4*      out4 = (float4*)(out + (size_t)plane * SS * KK);
    const float* cbase = centers + (size_t)b * SS * 3 + co;

    // this block handles plane float4s [half*8192, half*8192+8192)
    const int base = half * 8192;
    #pragma unroll 1
    for (int ii = 0; ii < 4; ++ii) {
        const int i0 = base + ii * 2048 + threadIdx.x;
        const int i1 = i0 + 512, i2 = i0 + 1024, i3 = i0 + 1536;

        const int4 d0 = __ldg(idx4 + i0);
        const int4 d1 = __ldg(idx4 + i1);
        const int4 d2 = __ldg(idx4 + i2);
        const int4 d3 = __ldg(idx4 + i3);

        float4 v0, v1, v2, v3;
        v0.x = row[d0.x]; v0.y = row[d0.y]; v0.z = row[d0.z]; v0.w = row[d0.w];
        v1.x = row[d1.x]; v1.y = row[d1.y]; v1.z = row[d1.z]; v1.w = row[d1.w];
        v2.x = row[d2.x]; v2.y = row[d2.y]; v2.z = row[d2.z]; v2.w = row[d2.w];
        v3.x = row[d3.x]; v3.y = row[d3.y]; v3.z = row[d3.z]; v3.w = row[d3.w];

        if (isxyz) {
            const float c0 = __ldg(cbase + 3 * (i0 >> 3));
            const float c1 = __ldg(cbase + 3 * (i1 >> 3));
            const float c2 = __ldg(cbase + 3 * (i2 >> 3));
            const float c3 = __ldg(cbase + 3 * (i3 >> 3));
            v0.x -= c0; v0.y -= c0; v0.z -= c0; v0.w -= c0;
            v1.x -= c1; v1.y -= c1; v1.z -= c1; v1.w -= c1;
            v2.x -= c2; v2.y -= c2; v2.z -= c2; v2.w -= c2;
            v3.x -= c3; v3.y -= c3; v3.z -= c3; v3.w -= c3;
        }

        out4[i0] = v0;
        out4[i1] = v1;
        out4[i2] = v2;
        out4[i3] = v3;
    }
}

// ---------------------------------------------------------------------------
extern "C" void kernel_launch(void* const* d_in, const int* in_sizes, int n_in,
                              void* d_out, int out_size)
{
    const float* points  = (const float*)d_in[0];  // 8*16384*3
    const float* centers = (const float*)d_in[1];  // 8*2048*3
    const float* feats   = (const float*)d_in[2];  // 8*64*16384
    float* out = (float*)d_out;                    // 8*67*2048*32

    (void)in_sizes; (void)n_in; (void)out_size;

    static_assert(NN * sizeof(float) == 65536, "row size");
    cudaFuncSetAttribute(gather_kernel,
                         cudaFuncAttributeMaxDynamicSharedMemorySize,
                         NN * (int)sizeof(float));

    ball_query_kernel<<<BB * SS / QW, 256>>>((const float4*)points, centers);
    gather_kernel<<<BB * COUT * 2, 512, NN * sizeof(float)>>>(points, centers, feats, out);
}

// round 7
// speedup vs baseline: 1.2987x; 1.2987x over previous
#include <cuda_runtime.h>
#include <stdint.h>

#define BB 8
#define NN 16384
#define SS 2048
#define CC 64
#define KK 32
#define COUT (3 + CC)      // 67
#define NG  (NN / 128)     // 128 groups of 128 points

// Scratch (no cudaMalloc allowed).
__device__ __align__(16) int   g_idx[BB * SS * KK];
__device__ __align__(16) float g_px[BB * NN];
__device__ __align__(16) float g_py[BB * NN];
__device__ __align__(16) float g_pz[BB * NN];

// ---------------------------------------------------------------------------
// Kernel 0: AoS (B,N,3) -> SoA px/py/pz. Tiny (~1.5MB traffic).
// ---------------------------------------------------------------------------
__global__ __launch_bounds__(256) void transpose_kernel(
    const float* __restrict__ points)
{
    const int i = blockIdx.x * blockDim.x + threadIdx.x;   // global point id
    if (i < BB * NN) {
        g_px[i] = __ldg(points + 3 * i + 0);
        g_py[i] = __ldg(points + 3 * i + 1);
        g_pz[i] = __ldg(points + 3 * i + 2);
    }
}

// ---------------------------------------------------------------------------
// Kernel 1: warp-per-center ball query over SoA points.
// Per 128-pt group: 3 perfectly-coalesced LDG.128 (12 L1 wavefronts, the
// minimum), 4 ballots, exact (non-FMA) distance math, prefetch 1 group ahead,
// warp-uniform early exit. Lane l owns points 4l..4l+3 of the group
// (lane-major ascending order -> R5-proven prefix math).
// Semantics: smallest 32 indices j with |c-p_j|^2 < 0.04 (ascending),
// padded with the first found index, or 0 if none found.
// ---------------------------------------------------------------------------
__global__ __launch_bounds__(256) void ball_query_kernel(
    const float* __restrict__ centers)   // (B, S, 3)
{
    const int wid  = threadIdx.x >> 5;
    const int lane = threadIdx.x & 31;
    const int gw   = blockIdx.x * 8 + wid;   // center id = b*S + s
    const int b    = gw / SS;

    const float* cptr = centers + (size_t)gw * 3;
    const float cx = __ldg(cptr + 0);
    const float cy = __ldg(cptr + 1);
    const float cz = __ldg(cptr + 2);

    __shared__ int sel[8][KK];

    const float4* px4 = (const float4*)(g_px + (size_t)b * NN);
    const float4* py4 = (const float4*)(g_py + (size_t)b * NN);
    const float4* pz4 = (const float4*)(g_pz + (size_t)b * NN);

    const float R2 = 0.04f;
    const unsigned below = (1u << lane) - 1u;

    int cnt = 0;

    // prefetch group 0  (f4 index: g*32 + lane)
    float4 ax = __ldg(px4 + lane);
    float4 ay = __ldg(py4 + lane);
    float4 az = __ldg(pz4 + lane);

    for (int g = 0; g < NG; ++g) {
        float4 bx = make_float4(0.f, 0.f, 0.f, 0.f);
        float4 by = bx, bz = bx;
        if (g + 1 < NG) {
            const int nf = (g + 1) * 32 + lane;
            bx = __ldg(px4 + nf); by = __ldg(py4 + nf); bz = __ldg(pz4 + nf);
        }

        float dx, dy, dz;
        #define DIST(PX,PY,PZ,DST)                                             \
            dx = __fadd_rn(cx, -(PX)); dy = __fadd_rn(cy, -(PY));              \
            dz = __fadd_rn(cz, -(PZ));                                         \
            DST = __fadd_rn(__fadd_rn(__fmul_rn(dx,dx), __fmul_rn(dy,dy)),     \
                            __fmul_rn(dz,dz));
        float q0, q1, q2, q3;
        DIST(ax.x, ay.x, az.x, q0);
        DIST(ax.y, ay.y, az.y, q1);
        DIST(ax.z, ay.z, az.z, q2);
        DIST(ax.w, ay.w, az.w, q3);
        #undef DIST

        const bool h0 = q0 < R2, h1 = q1 < R2, h2 = q2 < R2, h3 = q3 < R2;
        const unsigned m0 = __ballot_sync(0xffffffffu, h0);
        const unsigned m1 = __ballot_sync(0xffffffffu, h1);
        const unsigned m2 = __ballot_sync(0xffffffffu, h2);
        const unsigned m3 = __ballot_sync(0xffffffffu, h3);

        // ascending order: j = g*128 + 4*lane + c
        int p = cnt + __popc(m0 & below) + __popc(m1 & below)
                    + __popc(m2 & below) + __popc(m3 & below);
        const int j = g * 128 + 4 * lane;
        if (h0) { if (p < KK) sel[wid][p] = j + 0; p++; }
        if (h1) { if (p < KK) sel[wid][p] = j + 1; p++; }
        if (h2) { if (p < KK) sel[wid][p] = j + 2; p++; }
        if (h3) { if (p < KK) sel[wid][p] = j + 3; p++; }

        cnt += __popc(m0) + __popc(m1) + __popc(m2) + __popc(m3);
        if (cnt >= KK) break;   // warp-uniform

        ax = bx; ay = by; az = bz;
    }
    __syncwarp();

    int v;
    if (cnt == 0) {
        v = 0;
    } else {
        const int first = sel[wid][0];
        v = (lane < cnt) ? sel[wid][lane] : first;
    }
    g_idx[(size_t)gw * KK + lane] = v;
}

// ---------------------------------------------------------------------------
// Kernel 2: gather. Two blocks per (b, out-channel) plane. Stage the 64KB
// source row in dynamic smem (xyz rows now come coalesced from the SoA
// arrays), gather via LDS, coalesced float4 stores.
// ---------------------------------------------------------------------------
__global__ __launch_bounds__(512) void gather_kernel(
    const float* __restrict__ centers,  // (B, S, 3)
    const float* __restrict__ feats,    // (B, C, N)
    float* __restrict__ out)            // (B, 67, S, K)
{
    extern __shared__ float row[];      // NN floats = 64KB

    const int chunk = blockIdx.x;       // 0 .. B*67*2-1
    const int plane = chunk >> 1;
    const int half  = chunk & 1;
    const int b  = plane / COUT;
    const int co = plane % COUT;
    const bool isxyz = (co < 3);

    {
        const float* srcf =
            (co == 0) ? (g_px + (size_t)b * NN) :
            (co == 1) ? (g_py + (size_t)b * NN) :
            (co == 2) ? (g_pz + (size_t)b * NN) :
                        (feats + ((size_t)b * CC + (co - 3)) * NN);
        const float4* f4 = (const float4*)srcf;
        float4* r4 = (float4*)row;
        for (int i = threadIdx.x; i < NN / 4; i += blockDim.x)
            r4[i] = __ldg(f4 + i);
    }
    __syncthreads();

    const int4*  idx4 = (const int4*)(g_idx + (size_t)b * SS * KK);
    float4*      out4 = (float4*)(out + (size_t)plane * SS * KK);
    const float* cbase = centers + (size_t)b * SS * 3 + co;

    const int base = half * 8192;       // this block: float4s [base, base+8192)
    #pragma unroll 1
    for (int ii = 0; ii < 4; ++ii) {
        const int i0 = base + ii * 2048 + threadIdx.x;
        const int i1 = i0 + 512, i2 = i0 + 1024, i3 = i0 + 1536;

        const int4 d0 = __ldg(idx4 + i0);
        const int4 d1 = __ldg(idx4 + i1);
        const int4 d2 = __ldg(idx4 + i2);
        const int4 d3 = __ldg(idx4 + i3);

        float4 v0, v1, v2, v3;
        v0.x = row[d0.x]; v0.y = row[d0.y]; v0.z = row[d0.z]; v0.w = row[d0.w];
        v1.x = row[d1.x]; v1.y = row[d1.y]; v1.z = row[d1.z]; v1.w = row[d1.w];
        v2.x = row[d2.x]; v2.y = row[d2.y]; v2.z = row[d2.z]; v2.w = row[d2.w];
        v3.x = row[d3.x]; v3.y = row[d3.y]; v3.z = row[d3.z]; v3.w = row[d3.w];

        if (isxyz) {
            const float c0 = __ldg(cbase + 3 * (i0 >> 3));
            const float c1 = __ldg(cbase + 3 * (i1 >> 3));
            const float c2 = __ldg(cbase + 3 * (i2 >> 3));
            const float c3 = __ldg(cbase + 3 * (i3 >> 3));
            v0.x -= c0; v0.y -= c0; v0.z -= c0; v0.w -= c0;
            v1.x -= c1; v1.y -= c1; v1.z -= c1; v1.w -= c1;
            v2.x -= c2; v2.y -= c2; v2.z -= c2; v2.w -= c2;
            v3.x -= c3; v3.y -= c3; v3.z -= c3; v3.w -= c3;
        }

        out4[i0] = v0;
        out4[i1] = v1;
        out4[i2] = v2;
        out4[i3] = v3;
    }
}

// ---------------------------------------------------------------------------
extern "C" void kernel_launch(void* const* d_in, const int* in_sizes, int n_in,
                              void* d_out, int out_size)
{
    const float* points  = (const float*)d_in[0];  // 8*16384*3
    const float* centers = (const float*)d_in[1];  // 8*2048*3
    const float* feats   = (const float*)d_in[2];  // 8*64*16384
    float* out = (float*)d_out;                    // 8*67*2048*32

    (void)in_sizes; (void)n_in; (void)out_size;

    static_assert(NN * sizeof(float) == 65536, "row size");
    cudaFuncSetAttribute(gather_kernel,
                         cudaFuncAttributeMaxDynamicSharedMemorySize,
                         NN * (int)sizeof(float));

    transpose_kernel<<<(BB * NN + 255) / 256, 256>>>(points);
    ball_query_kernel<<<BB * SS / 8, 256>>>(centers);
    gather_kernel<<<BB * COUT * 2, 512, NN * sizeof(float)>>>(centers, feats, out);
}

// round 9
// speedup vs baseline: 1.4713x; 1.1329x over previous
#include <cuda_runtime.h>
#include <stdint.h>

#define BB 8
#define NN 16384
#define SS 2048
#define CC 64
#define KK 32
#define COUT (3 + CC)      // 67
#define NG2 (NN / 256)     // 64 iterations of 256 points

// Scratch (no cudaMalloc allowed).
__device__ __align__(16) int   g_idx[BB * SS * KK];
__device__ __align__(16) float g_px[BB * NN];
__device__ __align__(16) float g_py[BB * NN];
__device__ __align__(16) float g_pz[BB * NN];

// ---------------------------------------------------------------------------
// Kernel 0: AoS (B,N,3) -> SoA px/py/pz via smem tile; coalesced both ways.
// 128 blocks x 256 threads; each block transposes 1024 points (12KB).
// ---------------------------------------------------------------------------
__global__ __launch_bounds__(256) void transpose_kernel(
    const float4* __restrict__ pts4)    // (B*N*3)/4 float4s
{
    __shared__ float4 sm[768];          // 1024 points * 3 floats
    const int tid = threadIdx.x;
    const int blk = blockIdx.x;         // 0..127; 16 blocks per batch

    #pragma unroll
    for (int k = 0; k < 3; ++k)
        sm[tid + k * 256] = __ldg(pts4 + (size_t)blk * 768 + tid + k * 256);
    __syncthreads();

    const float* sf = (const float*)sm;
    const int lp = 12 * tid;            // local float base for points 4t..4t+3
    float4 vx, vy, vz;
    vx.x = sf[lp + 0]; vy.x = sf[lp + 1];  vz.x = sf[lp + 2];
    vx.y = sf[lp + 3]; vy.y = sf[lp + 4];  vz.y = sf[lp + 5];
    vx.z = sf[lp + 6]; vy.z = sf[lp + 7];  vz.z = sf[lp + 8];
    vx.w = sf[lp + 9]; vy.w = sf[lp + 10]; vz.w = sf[lp + 11];

    const int o = blk * 256 + tid;      // float4 index into SoA arrays
    ((float4*)g_px)[o] = vx;
    ((float4*)g_py)[o] = vy;
    ((float4*)g_pz)[o] = vz;
}

// ---------------------------------------------------------------------------
// Kernel 1: warp-per-center ball query over SoA points, 256 points/iter.
// 6 coalesced LDG.128 (prefetched one iteration ahead), 8 ballots, exact
// (non-FMA) distance math, warp-uniform early exit.
// Index order: j = g*256 + sub*128 + 4*lane + c (ascending).
// Semantics: smallest 32 indices j with |c-p_j|^2 < 0.04 (ascending),
// padded with the first found index, or 0 if none found.
// ---------------------------------------------------------------------------
__global__ __launch_bounds__(256) void ball_query_kernel(
    const float* __restrict__ centers)   // (B, S, 3)
{
    const int wid  = threadIdx.x >> 5;
    const int lane = threadIdx.x & 31;
    const int gw   = blockIdx.x * 8 + wid;   // center id = b*S + s
    const int b    = gw / SS;

    const float* cptr = centers + (size_t)gw * 3;
    const float cx = __ldg(cptr + 0);
    const float cy = __ldg(cptr + 1);
    const float cz = __ldg(cptr + 2);

    __shared__ int sel[8][KK];

    const float4* px4 = (const float4*)(g_px + (size_t)b * NN);
    const float4* py4 = (const float4*)(g_py + (size_t)b * NN);
    const float4* pz4 = (const float4*)(g_pz + (size_t)b * NN);

    const float R2 = 0.04f;
    const unsigned below = (1u << lane) - 1u;

    int cnt = 0;

    // prefetch iteration 0: f4 indices g*64 + lane (sub0) and +32 (sub1)
    float4 ax0 = __ldg(px4 + lane),      ay0 = __ldg(py4 + lane),      az0 = __ldg(pz4 + lane);
    float4 ax1 = __ldg(px4 + 32 + lane), ay1 = __ldg(py4 + 32 + lane), az1 = __ldg(pz4 + 32 + lane);

    for (int g = 0; g < NG2; ++g) {
        float4 bx0 = make_float4(0.f,0.f,0.f,0.f), by0 = bx0, bz0 = bx0;
        float4 bx1 = bx0, by1 = bx0, bz1 = bx0;
        if (g + 1 < NG2) {
            const int nf = (g + 1) * 64 + lane;
            bx0 = __ldg(px4 + nf);      by0 = __ldg(py4 + nf);      bz0 = __ldg(pz4 + nf);
            bx1 = __ldg(px4 + nf + 32); by1 = __ldg(py4 + nf + 32); bz1 = __ldg(pz4 + nf + 32);
        }

        float dx, dy, dz;
        #define DIST(PX,PY,PZ,DST)                                             \
            dx = __fadd_rn(cx, -(PX)); dy = __fadd_rn(cy, -(PY));              \
            dz = __fadd_rn(cz, -(PZ));                                         \
            DST = __fadd_rn(__fadd_rn(__fmul_rn(dx,dx), __fmul_rn(dy,dy)),     \
                            __fmul_rn(dz,dz));
        float q0,q1,q2,q3,q4,q5,q6,q7;
        DIST(ax0.x, ay0.x, az0.x, q0);
        DIST(ax0.y, ay0.y, az0.y, q1);
        DIST(ax0.z, ay0.z, az0.z, q2);
        DIST(ax0.w, ay0.w, az0.w, q3);
        DIST(ax1.x, ay1.x, az1.x, q4);
        DIST(ax1.y, ay1.y, az1.y, q5);
        DIST(ax1.z, ay1.z, az1.z, q6);
        DIST(ax1.w, ay1.w, az1.w, q7);
        #undef DIST

        const bool h0=q0<R2, h1=q1<R2, h2=q2<R2, h3=q3<R2;
        const bool h4=q4<R2, h5=q5<R2, h6=q6<R2, h7=q7<R2;
        const unsigned m0=__ballot_sync(0xffffffffu,h0), m1=__ballot_sync(0xffffffffu,h1);
        const unsigned m2=__ballot_sync(0xffffffffu,h2), m3=__ballot_sync(0xffffffffu,h3);
        const unsigned m4=__ballot_sync(0xffffffffu,h4), m5=__ballot_sync(0xffffffffu,h5);
        const unsigned m6=__ballot_sync(0xffffffffu,h6), m7=__ballot_sync(0xffffffffu,h7);

        const int t0 = __popc(m0)+__popc(m1)+__popc(m2)+__popc(m3);
        const int t1 = __popc(m4)+__popc(m5)+__popc(m6)+__popc(m7);

        // sub0: j = g*256 + 4*lane + c
        int p = cnt + __popc(m0&below)+__popc(m1&below)+__popc(m2&below)+__popc(m3&below);
        const int j0 = g * 256 + 4 * lane;
        if (h0) { if (p < KK) sel[wid][p] = j0 + 0; p++; }
        if (h1) { if (p < KK) sel[wid][p] = j0 + 1; p++; }
        if (h2) { if (p < KK) sel[wid][p] = j0 + 2; p++; }
        if (h3) { if (p < KK) sel[wid][p] = j0 + 3; p++; }
        // sub1: j = g*256 + 128 + 4*lane + c (all indices > sub0's)
        int q = cnt + t0 + __popc(m4&below)+__popc(m5&below)+__popc(m6&below)+__popc(m7&below);
        const int j1 = j0 + 128;
        if (h4) { if (q < KK) sel[wid][q] = j1 + 0; q++; }
        if (h5) { if (q < KK) sel[wid][q] = j1 + 1; q++; }
        if (h6) { if (q < KK) sel[wid][q] = j1 + 2; q++; }
        if (h7) { if (q < KK) sel[wid][q] = j1 + 3; q++; }

        cnt += t0 + t1;
        if (cnt >= KK) break;   // warp-uniform

        ax0 = bx0; ay0 = by0; az0 = bz0;
        ax1 = bx1; ay1 = by1; az1 = bz1;
    }
    __syncwarp();

    int v;
    if (cnt == 0) {
        v = 0;
    } else {
        const int first = sel[wid][0];
        v = (lane < cnt) ? sel[wid][lane] : first;
    }
    g_idx[(size_t)gw * KK + lane] = v;
}

// ---------------------------------------------------------------------------
// Kernel 2: gather. Four chunks per (b, out-channel) plane. Stage the 64KB
// source row via cp.async (L1-bypassing LDGSTS, no register roundtrip),
// gather via LDS, coalesced float4 stores.
// ---------------------------------------------------------------------------
__device__ __forceinline__ void cp_async16(uint32_t dst_smem, const void* src) {
    asm volatile("cp.async.cg.shared.global [%0], [%1], 16;\n"
                 :: "r"(dst_smem), "l"(src) : "memory");
}

__global__ __launch_bounds__(512) void gather_kernel(
    const float* __restrict__ centers,  // (B, S, 3)
    const float* __restrict__ feats,    // (B, C, N)
    float* __restrict__ out)            // (B, 67, S, K)
{
    extern __shared__ float row[];      // NN floats = 64KB

    const int chunk = blockIdx.x;       // 0 .. B*67*4-1
    const int plane = chunk >> 2;
    const int quart = chunk & 3;
    const int b  = plane / COUT;
    const int co = plane % COUT;
    const bool isxyz = (co < 3);

    {
        const float* srcf =
            (co == 0) ? (g_px + (size_t)b * NN) :
            (co == 1) ? (g_py + (size_t)b * NN) :
            (co == 2) ? (g_pz + (size_t)b * NN) :
                        (feats + ((size_t)b * CC + (co - 3)) * NN);
        uint32_t rbase;
        asm("{ .reg .u64 t; cvta.to.shared.u64 t, %1; cvt.u32.u64 %0, t; }"
            : "=r"(rbase) : "l"(row));
        // 4096 float4s, 512 threads -> 8 cp.async each
        #pragma unroll
        for (int k = 0; k < 8; ++k) {
            const int i = threadIdx.x + k * 512;
            cp_async16(rbase + 16u * i, (const float4*)srcf + i);
        }
        asm volatile("cp.async.commit_group;\n" ::: "memory");
        asm volatile("cp.async.wait_group 0;\n" ::: "memory");
    }
    __syncthreads();

    const int4*  idx4 = (const int4*)(g_idx + (size_t)b * SS * KK);
    float4*      out4 = (float4*)(out + (size_t)plane * SS * KK);
    const float* cbase = centers + (size_t)b * SS * 3 + co;

    const int base = quart * 4096;      // this block: float4s [base, base+4096)
    #pragma unroll 1
    for (int ii = 0; ii < 2; ++ii) {
        const int i0 = base + ii * 2048 + threadIdx.x;
        const int i1 = i0 + 512, i2 = i0 + 1024, i3 = i0 + 1536;

        const int4 d0 = __ldg(idx4 + i0);
        const int4 d1 = __ldg(idx4 + i1);
        const int4 d2 = __ldg(idx4 + i2);
        const int4 d3 = __ldg(idx4 + i3);

        float4 v0, v1, v2, v3;
        v0.x = row[d0.x]; v0.y = row[d0.y]; v0.z = row[d0.z]; v0.w = row[d0.w];
        v1.x = row[d1.x]; v1.y = row[d1.y]; v1.z = row[d1.z]; v1.w = row[d1.w];
        v2.x = row[d2.x]; v2.y = row[d2.y]; v2.z = row[d2.z]; v2.w = row[d2.w];
        v3.x = row[d3.x]; v3.y = row[d3.y]; v3.z = row[d3.z]; v3.w = row[d3.w];

        if (isxyz) {
            const float c0 = __ldg(cbase + 3 * (i0 >> 3));
            const float c1 = __ldg(cbase + 3 * (i1 >> 3));
            const float c2 = __ldg(cbase + 3 * (i2 >> 3));
            const float c3 = __ldg(cbase + 3 * (i3 >> 3));
            v0.x -= c0; v0.y -= c0; v0.z -= c0; v0.w -= c0;
            v1.x -= c1; v1.y -= c1; v1.z -= c1; v1.w -= c1;
            v2.x -= c2; v2.y -= c2; v2.z -= c2; v2.w -= c2;
            v3.x -= c3; v3.y -= c3; v3.z -= c3; v3.w -= c3;
        }

        out4[i0] = v0;
        out4[i1] = v1;
        out4[i2] = v2;
        out4[i3] = v3;
    }
}

// ---------------------------------------------------------------------------
extern "C" void kernel_launch(void* const* d_in, const int* in_sizes, int n_in,
                              void* d_out, int out_size)
{
    const float* points  = (const float*)d_in[0];  // 8*16384*3
    const float* centers = (const float*)d_in[1];  // 8*2048*3
    const float* feats   = (const float*)d_in[2];  // 8*64*16384
    float* out = (float*)d_out;                    // 8*67*2048*32

    (void)in_sizes; (void)n_in; (void)out_size;

    static_assert(NN * sizeof(float) == 65536, "row size");
    cudaFuncSetAttribute(gather_kernel,
                         cudaFuncAttributeMaxDynamicSharedMemorySize,
                         NN * (int)sizeof(float));

    transpose_kernel<<<BB * NN / 1024, 256>>>((const float4*)points);
    ball_query_kernel<<<BB * SS / 8, 256>>>(centers);
    gather_kernel<<<BB * COUT * 4, 512, NN * sizeof(float)>>>(centers, feats, out);
}